// round 14
// baseline (speedup 1.0000x reference)
#include <cuda_runtime.h>
#include <cuda_fp16.h>
#include <math.h>
#include <stdint.h>
#include <cstdint>

#define N_NODES 50000
#define N_EDGES 800000
#define D 128
#define SCALEF 0.17677669529663687f   // 32^-0.5
#define EPSF 1e-7f
#define SCAN_BLOCKS ((N_NODES + 255) / 256)       // 196
#define HIST_BLOCKS ((N_EDGES + 255) / 256)       // 3125
#define LOG_BLOCKS  ((N_NODES * 32 + 255) / 256)  // 6250
#define GEMM_BX     ((N_NODES + 127) / 128)       // 391
#define QKV_BLOCKS  (GEMM_BX * 3)                 // 1173
#define SCAT_BLOCKS 640

// ---------------- static device scratch ----------------
__device__ __half g_xtanh[(size_t)N_NODES * D];      // x_tan fp16
__device__ __half g_wh[4 * D * D];                   // Wq|Wk|Wv|Wo fp16
__device__ __half g_qh[(size_t)N_NODES * D];         // Q fp16
__device__ __half g_kvh[(size_t)N_NODES * 2 * D];    // K(128)|V(128) fp16 per node
__device__ __half g_aggh[(size_t)N_NODES * D];       // attention out fp16, normalized
__device__ int    g_rowbuf[N_EDGES];
__device__ int    g_colbuf[N_EDGES];
__device__ int    g_cnt[N_NODES];
__device__ int    g_off[N_NODES + 1];
__device__ int    g_cur[N_NODES];
__device__ int    g_esort[N_EDGES];
__device__ int    g_bsum[SCAN_BLOCKS];
__device__ int    g_boff[SCAN_BLOCKS];
__device__ int    g_is64;

// ---------------- prep: edge dtype detect + zero cnt + cvt W ----------------
__global__ __launch_bounds__(256)
void k_prep(const unsigned int* __restrict__ w,
            const float* __restrict__ Wq, const float* __restrict__ Wk,
            const float* __restrict__ Wv, const float* __restrict__ Wo) {
    int i = blockIdx.x * 256 + threadIdx.x;
    if (i == 0) {
        int all0 = 1;
        #pragma unroll
        for (int j = 0; j < 32; j++) all0 &= (w[2 * j + 1] == 0u);
        g_is64 = all0;
    }
    if (i < N_NODES) g_cnt[i] = 0;
    if (i < 4 * D * D) {
        int sel = i / (D * D);
        int off = i - sel * (D * D);
        float v = (sel == 0) ? Wq[off] : (sel == 1) ? Wk[off] : (sel == 2) ? Wv[off] : Wo[off];
        g_wh[i] = __float2half_rn(v);
    }
}

// ---------------- fused: edge cvt+hist (blocks<HIST) || logmap (rest) ------
__global__ __launch_bounds__(256)
void k_hist_log(const void* __restrict__ eiv, const float* __restrict__ x) {
    if (blockIdx.x < HIST_BLOCKS) {
        int e = blockIdx.x * 256 + threadIdx.x;
        if (e >= N_EDGES) return;
        int r, c;
        if (g_is64) {
            const long long* ei = (const long long*)eiv;
            r = (int)ei[e];
            c = (int)ei[N_EDGES + e];
        } else {
            const int* ei = (const int*)eiv;
            r = ei[e];
            c = ei[N_EDGES + e];
        }
        g_rowbuf[e] = r;
        g_colbuf[e] = c;
        atomicAdd(&g_cnt[c], 1);
        return;
    }
    int gw = ((blockIdx.x - HIST_BLOCKS) * 256 + threadIdx.x) >> 5;
    int lane = threadIdx.x & 31;
    if (gw >= N_NODES) return;
    const float* xr = x + (size_t)gw * 129;
    float a0 = xr[1 + 4 * lane + 0];
    float a1 = xr[1 + 4 * lane + 1];
    float a2 = xr[1 + 4 * lane + 2];
    float a3 = xr[1 + 4 * lane + 3];
    float ss = a0 * a0 + a1 * a1 + a2 * a2 + a3 * a3;
    #pragma unroll
    for (int o = 16; o >= 1; o >>= 1) ss += __shfl_xor_sync(0xFFFFFFFFu, ss, o);
    float norm = sqrtf(ss + EPSF);
    float fac = acoshf(fmaxf(xr[0], 1.0f + EPSF)) / norm;
    __half2 h0 = __float22half2_rn(make_float2(fac * a0, fac * a1));
    __half2 h1 = __float22half2_rn(make_float2(fac * a2, fac * a3));
    uint2 u;
    u.x = *reinterpret_cast<unsigned int*>(&h0);
    u.y = *reinterpret_cast<unsigned int*>(&h1);
    *(uint2*)(g_xtanh + (size_t)gw * D + 4 * lane) = u;
}

// ---------------- parallel scan (3 phases) ----------------
__global__ __launch_bounds__(256)
void k_scanA() {
    int tid = threadIdx.x;
    int i = blockIdx.x * 256 + tid;
    int v = (i < N_NODES) ? g_cnt[i] : 0;
    int lane = tid & 31, wid = tid >> 5;
    int s = v;
    #pragma unroll
    for (int o = 1; o < 32; o <<= 1) {
        int t = __shfl_up_sync(0xFFFFFFFFu, s, o);
        if (lane >= o) s += t;
    }
    __shared__ int wsum[8];
    if (lane == 31) wsum[wid] = s;
    __syncthreads();
    if (wid == 0) {
        int ws = (lane < 8) ? wsum[lane] : 0;
        #pragma unroll
        for (int o = 1; o < 8; o <<= 1) {
            int t = __shfl_up_sync(0xFFFFFFFFu, ws, o);
            if (lane >= o) ws += t;
        }
        if (lane < 8) wsum[lane] = ws;
    }
    __syncthreads();
    int inc = s + ((wid > 0) ? wsum[wid - 1] : 0);
    if (i < N_NODES) g_off[i] = inc - v;
    if (tid == 255) g_bsum[blockIdx.x] = inc;
}

__global__ __launch_bounds__(256)
void k_scanB() {
    int tid = threadIdx.x;
    int v = (tid < SCAN_BLOCKS) ? g_bsum[tid] : 0;
    int lane = tid & 31, wid = tid >> 5;
    int s = v;
    #pragma unroll
    for (int o = 1; o < 32; o <<= 1) {
        int t = __shfl_up_sync(0xFFFFFFFFu, s, o);
        if (lane >= o) s += t;
    }
    __shared__ int wsum[8];
    if (lane == 31) wsum[wid] = s;
    __syncthreads();
    if (wid == 0) {
        int ws = (lane < 8) ? wsum[lane] : 0;
        #pragma unroll
        for (int o = 1; o < 8; o <<= 1) {
            int t = __shfl_up_sync(0xFFFFFFFFu, ws, o);
            if (lane >= o) ws += t;
        }
        if (lane < 8) wsum[lane] = ws;
    }
    __syncthreads();
    int inc = s + ((wid > 0) ? wsum[wid - 1] : 0);
    if (tid < SCAN_BLOCKS) g_boff[tid] = inc - v;
}

__global__ __launch_bounds__(256)
void k_scanC() {
    int i = blockIdx.x * 256 + threadIdx.x;
    if (i < N_NODES) {
        int o = g_off[i] + g_boff[blockIdx.x];
        g_off[i] = o;
        g_cur[i] = o;
    }
    if (i == 0) g_off[N_NODES] = N_EDGES;
}

// ---------------- fused: QKV mma GEMM (blocks<QKV_BLOCKS) || scatter -------
__global__ __launch_bounds__(256, 2)
void k_scatter_qkv(const __half* __restrict__ A,
                   __half* __restrict__ Qh, __half* __restrict__ KV, int M) {
    __shared__ __half As[128][72];
    __shared__ __half Bs[128][72];
    if (blockIdx.x >= QKV_BLOCKS) {
        // CSR scatter, grid-stride
        int tid = threadIdx.x;
        for (int e = (blockIdx.x - QKV_BLOCKS) * 256 + tid; e < N_EDGES;
             e += SCAT_BLOCKS * 256) {
            int c = g_colbuf[e];
            int pos = atomicAdd(&g_cur[c], 1);
            g_esort[pos] = g_rowbuf[e];
        }
        return;
    }
    int sel = blockIdx.x / GEMM_BX;
    int bx  = blockIdx.x - sel * GEMM_BX;
    const __half* W = g_wh + (size_t)sel * D * D;
    int t = threadIdx.x;
    int warp = t >> 5, lane = t & 31;
    int warp_m = warp & 3;
    int warp_n = warp >> 2;
    int rowBase = bx * 128;

    float acc[2][8][4];
    #pragma unroll
    for (int i = 0; i < 2; i++)
        #pragma unroll
        for (int j = 0; j < 8; j++)
            #pragma unroll
            for (int k = 0; k < 4; k++) acc[i][j][k] = 0.f;

    for (int k0 = 0; k0 < 128; k0 += 64) {
        __syncthreads();
        #pragma unroll
        for (int c = t; c < 1024; c += 256) {
            int r = c >> 3, c8 = (c & 7) * 8;
            int gr = rowBase + r;
            uint4 va = make_uint4(0u, 0u, 0u, 0u);
            if (gr < M) va = *(const uint4*)&A[(size_t)gr * 128 + k0 + c8];
            *(uint4*)&As[r][c8] = va;
            uint4 vb = *(const uint4*)&W[(size_t)r * 128 + k0 + c8];
            *(uint4*)&Bs[r][c8] = vb;
        }
        __syncthreads();
        #pragma unroll
        for (int kk = 0; kk < 4; kk++) {
            uint32_t af[2][4];
            #pragma unroll
            for (int mt = 0; mt < 2; mt++) {
                int sub = lane >> 3;
                int row = warp_m * 32 + mt * 16 + ((sub & 1) * 8) + (lane & 7);
                int col = kk * 16 + ((sub >> 1) * 8);
                uint32_t addr = (uint32_t)__cvta_generic_to_shared(&As[row][col]);
                asm volatile("ldmatrix.sync.aligned.m8n8.x4.shared.b16 {%0,%1,%2,%3}, [%4];"
                    : "=r"(af[mt][0]), "=r"(af[mt][1]), "=r"(af[mt][2]), "=r"(af[mt][3])
                    : "r"(addr));
            }
            uint32_t bf[8][2];
            #pragma unroll
            for (int np = 0; np < 4; np++) {
                int sub = lane >> 3;
                int row = warp_n * 64 + np * 16 + ((sub >> 1) * 8) + (lane & 7);
                int col = kk * 16 + ((sub & 1) * 8);
                uint32_t r0, r1, r2, r3;
                uint32_t addr = (uint32_t)__cvta_generic_to_shared(&Bs[row][col]);
                asm volatile("ldmatrix.sync.aligned.m8n8.x4.shared.b16 {%0,%1,%2,%3}, [%4];"
                    : "=r"(r0), "=r"(r1), "=r"(r2), "=r"(r3) : "r"(addr));
                bf[np * 2][0] = r0; bf[np * 2][1] = r1;
                bf[np * 2 + 1][0] = r2; bf[np * 2 + 1][1] = r3;
            }
            #pragma unroll
            for (int mt = 0; mt < 2; mt++)
                #pragma unroll
                for (int nt = 0; nt < 8; nt++)
                    asm volatile("mma.sync.aligned.m16n8k16.row.col.f32.f16.f16.f32 "
                        "{%0,%1,%2,%3}, {%4,%5,%6,%7}, {%8,%9}, {%0,%1,%2,%3};"
                        : "+f"(acc[mt][nt][0]), "+f"(acc[mt][nt][1]),
                          "+f"(acc[mt][nt][2]), "+f"(acc[mt][nt][3])
                        : "r"(af[mt][0]), "r"(af[mt][1]), "r"(af[mt][2]), "r"(af[mt][3]),
                          "r"(bf[nt][0]), "r"(bf[nt][1]));
        }
    }
    int g = lane >> 2, tg = lane & 3;
    #pragma unroll
    for (int mt = 0; mt < 2; mt++) {
        int r0 = rowBase + warp_m * 32 + mt * 16 + g;
        int r1 = r0 + 8;
        #pragma unroll
        for (int nt = 0; nt < 8; nt++) {
            int col = warp_n * 64 + nt * 8 + tg * 2;
            __half2 h0 = __float22half2_rn(make_float2(acc[mt][nt][0], acc[mt][nt][1]));
            __half2 h1 = __float22half2_rn(make_float2(acc[mt][nt][2], acc[mt][nt][3]));
            if (sel == 0) {
                if (r0 < M) *(__half2*)&Qh[(size_t)r0 * 128 + col] = h0;
                if (r1 < M) *(__half2*)&Qh[(size_t)r1 * 128 + col] = h1;
            } else {
                int off = (sel - 1) * 128;
                if (r0 < M) *(__half2*)&KV[(size_t)r0 * 256 + off + col] = h0;
                if (r1 < M) *(__half2*)&KV[(size_t)r1 * 256 + off + col] = h1;
            }
        }
    }
}

// ---------------- fp16 gather helper ----------------
__device__ __forceinline__ float4 ld4h(const __half* p) {
    uint2 u = *(const uint2*)p;
    __half2 h0 = *reinterpret_cast<__half2*>(&u.x);
    __half2 h1 = *reinterpret_cast<__half2*>(&u.y);
    float2 f0 = __half22float2(h0);
    float2 f1 = __half22float2(h1);
    return make_float4(f0.x, f0.y, f1.x, f1.y);
}

// ---------------- CSR aggregation: warp per dst, 4-way unroll, fp16 I/O ----
__global__ __launch_bounds__(256)
void k_agg() {
    int gw = (blockIdx.x * blockDim.x + threadIdx.x) >> 5;
    int lane = threadIdx.x & 31;
    if (gw >= N_NODES) return;
    int start = g_off[gw];
    int end   = g_off[gw + 1];
    float4 q = ld4h(g_qh + (size_t)gw * 128 + 4 * lane);
    float4 acc = make_float4(0.f, 0.f, 0.f, 0.f);
    float dsum = 0.f;
    int i = start;
    for (; i + 4 <= end; i += 4) {
        int s0 = g_esort[i], s1 = g_esort[i + 1], s2 = g_esort[i + 2], s3 = g_esort[i + 3];
        const __half* b0 = g_kvh + (size_t)s0 * 256;
        const __half* b1 = g_kvh + (size_t)s1 * 256;
        const __half* b2 = g_kvh + (size_t)s2 * 256;
        const __half* b3 = g_kvh + (size_t)s3 * 256;
        float4 k0 = ld4h(b0 + 4 * lane);
        float4 k1 = ld4h(b1 + 4 * lane);
        float4 k2 = ld4h(b2 + 4 * lane);
        float4 k3 = ld4h(b3 + 4 * lane);
        float p0 = q.x * k0.x + q.y * k0.y + q.z * k0.z + q.w * k0.w;
        float p1 = q.x * k1.x + q.y * k1.y + q.z * k1.z + q.w * k1.w;
        float p2 = q.x * k2.x + q.y * k2.y + q.z * k2.z + q.w * k2.w;
        float p3 = q.x * k3.x + q.y * k3.y + q.z * k3.z + q.w * k3.w;
        #pragma unroll
        for (int o = 4; o >= 1; o >>= 1) {
            p0 += __shfl_xor_sync(0xFFFFFFFFu, p0, o);
            p1 += __shfl_xor_sync(0xFFFFFFFFu, p1, o);
            p2 += __shfl_xor_sync(0xFFFFFFFFu, p2, o);
            p3 += __shfl_xor_sync(0xFFFFFFFFu, p3, o);
        }
        float e0 = __expf(p0 * SCALEF);
        float e1 = __expf(p1 * SCALEF);
        float e2 = __expf(p2 * SCALEF);
        float e3 = __expf(p3 * SCALEF);
        float4 v0 = ld4h(b0 + 128 + 4 * lane);
        float4 v1 = ld4h(b1 + 128 + 4 * lane);
        float4 v2 = ld4h(b2 + 128 + 4 * lane);
        float4 v3 = ld4h(b3 + 128 + 4 * lane);
        dsum += (e0 + e1) + (e2 + e3);
        acc.x = fmaf(e0, v0.x, fmaf(e1, v1.x, fmaf(e2, v2.x, fmaf(e3, v3.x, acc.x))));
        acc.y = fmaf(e0, v0.y, fmaf(e1, v1.y, fmaf(e2, v2.y, fmaf(e3, v3.y, acc.y))));
        acc.z = fmaf(e0, v0.z, fmaf(e1, v1.z, fmaf(e2, v2.z, fmaf(e3, v3.z, acc.z))));
        acc.w = fmaf(e0, v0.w, fmaf(e1, v1.w, fmaf(e2, v2.w, fmaf(e3, v3.w, acc.w))));
    }
    for (; i < end; i++) {
        int s0 = g_esort[i];
        const __half* b0 = g_kvh + (size_t)s0 * 256;
        float4 k0 = ld4h(b0 + 4 * lane);
        float p0 = q.x * k0.x + q.y * k0.y + q.z * k0.z + q.w * k0.w;
        #pragma unroll
        for (int o = 4; o >= 1; o >>= 1) p0 += __shfl_xor_sync(0xFFFFFFFFu, p0, o);
        float e0 = __expf(p0 * SCALEF);
        float4 v0 = ld4h(b0 + 128 + 4 * lane);
        dsum += e0;
        acc.x = fmaf(e0, v0.x, acc.x);
        acc.y = fmaf(e0, v0.y, acc.y);
        acc.z = fmaf(e0, v0.z, acc.z);
        acc.w = fmaf(e0, v0.w, acc.w);
    }
    float inv = (dsum > 0.f) ? (1.0f / dsum) : 0.f;
    __half2 h0 = __float22half2_rn(make_float2(acc.x * inv, acc.y * inv));
    __half2 h1 = __float22half2_rn(make_float2(acc.z * inv, acc.w * inv));
    uint2 u;
    u.x = *reinterpret_cast<unsigned int*>(&h0);
    u.y = *reinterpret_cast<unsigned int*>(&h1);
    *(uint2*)(g_aggh + (size_t)gw * 128 + 4 * lane) = u;
}

// ---------------- output GEMM (mma) fused with exp map -> final out --------
// Tile kept in 64KB dynamic smem fp32; per-row norm via warp reduce; writes (N,129).
__global__ __launch_bounds__(256, 2)
void k_gemmO_exp(const __half* __restrict__ A, const float* __restrict__ bias,
                 float* __restrict__ out, int M) {
    __shared__ __half As[128][72];
    __shared__ __half Bs[128][72];
    extern __shared__ float Cs[];   // 128 * 128 fp32
    const __half* W = g_wh + (size_t)3 * D * D;
    int t = threadIdx.x;
    int warp = t >> 5, lane = t & 31;
    int warp_m = warp & 3;
    int warp_n = warp >> 2;
    int rowBase = blockIdx.x * 128;

    float acc[2][8][4];
    #pragma unroll
    for (int i = 0; i < 2; i++)
        #pragma unroll
        for (int j = 0; j < 8; j++)
            #pragma unroll
            for (int k = 0; k < 4; k++) acc[i][j][k] = 0.f;

    for (int k0 = 0; k0 < 128; k0 += 64) {
        __syncthreads();
        #pragma unroll
        for (int c = t; c < 1024; c += 256) {
            int r = c >> 3, c8 = (c & 7) * 8;
            int gr = rowBase + r;
            uint4 va = make_uint4(0u, 0u, 0u, 0u);
            if (gr < M) va = *(const uint4*)&A[(size_t)gr * 128 + k0 + c8];
            *(uint4*)&As[r][c8] = va;
            uint4 vb = *(const uint4*)&W[(size_t)r * 128 + k0 + c8];
            *(uint4*)&Bs[r][c8] = vb;
        }
        __syncthreads();
        #pragma unroll
        for (int kk = 0; kk < 4; kk++) {
            uint32_t af[2][4];
            #pragma unroll
            for (int mt = 0; mt < 2; mt++) {
                int sub = lane >> 3;
                int row = warp_m * 32 + mt * 16 + ((sub & 1) * 8) + (lane & 7);
                int col = kk * 16 + ((sub >> 1) * 8);
                uint32_t addr = (uint32_t)__cvta_generic_to_shared(&As[row][col]);
                asm volatile("ldmatrix.sync.aligned.m8n8.x4.shared.b16 {%0,%1,%2,%3}, [%4];"
                    : "=r"(af[mt][0]), "=r"(af[mt][1]), "=r"(af[mt][2]), "=r"(af[mt][3])
                    : "r"(addr));
            }
            uint32_t bf[8][2];
            #pragma unroll
            for (int np = 0; np < 4; np++) {
                int sub = lane >> 3;
                int row = warp_n * 64 + np * 16 + ((sub >> 1) * 8) + (lane & 7);
                int col = kk * 16 + ((sub & 1) * 8);
                uint32_t r0, r1, r2, r3;
                uint32_t addr = (uint32_t)__cvta_generic_to_shared(&Bs[row][col]);
                asm volatile("ldmatrix.sync.aligned.m8n8.x4.shared.b16 {%0,%1,%2,%3}, [%4];"
                    : "=r"(r0), "=r"(r1), "=r"(r2), "=r"(r3) : "r"(addr));
                bf[np * 2][0] = r0; bf[np * 2][1] = r1;
                bf[np * 2 + 1][0] = r2; bf[np * 2 + 1][1] = r3;
            }
            #pragma unroll
            for (int mt = 0; mt < 2; mt++)
                #pragma unroll
                for (int nt = 0; nt < 8; nt++)
                    asm volatile("mma.sync.aligned.m16n8k16.row.col.f32.f16.f16.f32 "
                        "{%0,%1,%2,%3}, {%4,%5,%6,%7}, {%8,%9}, {%0,%1,%2,%3};"
                        : "+f"(acc[mt][nt][0]), "+f"(acc[mt][nt][1]),
                          "+f"(acc[mt][nt][2]), "+f"(acc[mt][nt][3])
                        : "r"(af[mt][0]), "r"(af[mt][1]), "r"(af[mt][2]), "r"(af[mt][3]),
                          "r"(bf[nt][0]), "r"(bf[nt][1]));
        }
    }
    // epilogue: bias + stash tile in smem fp32
    __syncthreads();   // As/Bs no longer needed; Cs independent buffer anyway
    int g = lane >> 2, tg = lane & 3;
    #pragma unroll
    for (int mt = 0; mt < 2; mt++) {
        int lr0 = warp_m * 32 + mt * 16 + g;
        int lr1 = lr0 + 8;
        #pragma unroll
        for (int nt = 0; nt < 8; nt++) {
            int col = warp_n * 64 + nt * 8 + tg * 2;
            float b0 = bias[col], b1 = bias[col + 1];
            Cs[lr0 * 128 + col]     = acc[mt][nt][0] + b0;
            Cs[lr0 * 128 + col + 1] = acc[mt][nt][1] + b1;
            Cs[lr1 * 128 + col]     = acc[mt][nt][2] + b0;
            Cs[lr1 * 128 + col + 1] = acc[mt][nt][3] + b1;
        }
    }
    __syncthreads();
    // exp map: warp w handles rows w*16 .. w*16+15
    for (int rr = warp * 16; rr < warp * 16 + 16; rr++) {
        int gr = rowBase + rr;
        if (gr >= M) break;
        float4 v = *(const float4*)&Cs[rr * 128 + 4 * lane];
        float ss = v.x * v.x + v.y * v.y + v.z * v.z + v.w * v.w;
        #pragma unroll
        for (int o = 16; o >= 1; o >>= 1) ss += __shfl_xor_sync(0xFFFFFFFFu, ss, o);
        float r = sqrtf(ss + EPSF);
        float x0 = coshf(r);
        float fac = sinhf(r) / r;
        float* orow = out + (size_t)gr * 129;
        if (lane == 0) orow[0] = x0;
        orow[1 + 4 * lane + 0] = fac * v.x;
        orow[1 + 4 * lane + 1] = fac * v.y;
        orow[1 + 4 * lane + 2] = fac * v.z;
        orow[1 + 4 * lane + 3] = fac * v.w;
    }
}

// ---------------- launch ----------------
extern "C" void kernel_launch(void* const* d_in, const int* in_sizes, int n_in,
                              void* d_out, int out_size) {
    const float* x  = (const float*)d_in[0];
    const void*  ei = (const void*)d_in[1];
    const float* Wq = (const float*)d_in[2];
    const float* Wk = (const float*)d_in[3];
    const float* Wv = (const float*)d_in[4];
    const float* Wo = (const float*)d_in[5];
    const float* bo = (const float*)d_in[6];
    float* out      = (float*)d_out;
    (void)in_sizes; (void)n_in; (void)out_size;

    // real device addresses of __device__ globals (ATS pitfall!)
    __half *xtanh, *qh, *kvh, *aggh;
    cudaGetSymbolAddress((void**)&xtanh, g_xtanh);
    cudaGetSymbolAddress((void**)&qh,    g_qh);
    cudaGetSymbolAddress((void**)&kvh,   g_kvh);
    cudaGetSymbolAddress((void**)&aggh,  g_aggh);

    // opt-in to 64KB dynamic smem for the fused output kernel (idempotent)
    cudaFuncSetAttribute(k_gemmO_exp, cudaFuncAttributeMaxDynamicSharedMemorySize,
                         128 * 128 * (int)sizeof(float));

    // 1. prep: dtype detect + zero hist + W->fp16
    k_prep<<<(4 * D * D + 255) / 256, 256>>>((const unsigned int*)ei, Wq, Wk, Wv, Wo);
    // 2. fused: edge cvt+hist || logmap
    k_hist_log<<<HIST_BLOCKS + LOG_BLOCKS, 256>>>(ei, x);
    // 3-5. CSR offsets
    k_scanA<<<SCAN_BLOCKS, 256>>>();
    k_scanB<<<1, 256>>>();
    k_scanC<<<SCAN_BLOCKS, 256>>>();
    // 6. fused: QKV mma GEMM || CSR scatter
    k_scatter_qkv<<<QKV_BLOCKS + SCAT_BLOCKS, 256>>>(xtanh, qh, kvh, N_NODES);
    // 7. attention aggregation
    k_agg<<<(N_NODES * 32 + 255) / 256, 256>>>();
    // 8. output projection + exp map -> final output
    k_gemmO_exp<<<GEMM_BX, 256, 128 * 128 * sizeof(float)>>>(aggh, bo, out, N_NODES);
}

// round 16
// speedup vs baseline: 1.4041x; 1.4041x over previous
#include <cuda_runtime.h>
#include <cuda_fp16.h>
#include <math.h>
#include <stdint.h>
#include <cstdint>

#define N_NODES 50000
#define N_EDGES 800000
#define D 128
#define SCALEF 0.17677669529663687f   // 32^-0.5
#define EPSF 1e-7f
#define SCAN_BLOCKS ((N_NODES + 255) / 256)   // 196

// ---------------- static device scratch ----------------
__device__ __half g_xtanh[(size_t)N_NODES * D];      // x_tan fp16 (GEMM A)
__device__ __half g_wh[4 * D * D];                   // Wq|Wk|Wv|Wo fp16
__device__ __half g_qh[(size_t)N_NODES * D];         // Q fp16
__device__ __half g_kvh[(size_t)N_NODES * 2 * D];    // per node: K(128)|V(128) fp16
__device__ __half g_aggh[(size_t)N_NODES * D];       // attention out fp16, normalized
__device__ float  g_otan[(size_t)N_NODES * D];
__device__ int    g_rowbuf[N_EDGES];
__device__ int    g_colbuf[N_EDGES];
__device__ int    g_cnt[N_NODES];
__device__ int    g_off[N_NODES + 1];
__device__ int    g_cur[N_NODES];
__device__ int    g_esort[N_EDGES];
__device__ int    g_bsum[SCAN_BLOCKS];
__device__ int    g_boff[SCAN_BLOCKS];
__device__ int    g_is64;

// ---------------- prep: edge dtype detect + zero cnt + cvt W ----------------
// MUST be launched with >= max(N_NODES, 4*D*D) = 65536 threads.
__global__ __launch_bounds__(256)
void k_prep(const unsigned int* __restrict__ w,
            const float* __restrict__ Wq, const float* __restrict__ Wk,
            const float* __restrict__ Wv, const float* __restrict__ Wo) {
    int i = blockIdx.x * 256 + threadIdx.x;
    if (i == 0) {
        int all0 = 1;
        #pragma unroll
        for (int j = 0; j < 32; j++) all0 &= (w[2 * j + 1] == 0u);
        g_is64 = all0;
    }
    if (i < N_NODES) g_cnt[i] = 0;
    if (i < 4 * D * D) {
        int sel = i / (D * D);
        int off = i - sel * (D * D);
        float v = (sel == 0) ? Wq[off] : (sel == 1) ? Wk[off] : (sel == 2) ? Wv[off] : Wo[off];
        g_wh[i] = __float2half_rn(v);
    }
}

// ---------------- convert edges + histogram dst degrees ----------------
__global__ void k_cvt_hist(const void* __restrict__ eiv) {
    int e = blockIdx.x * blockDim.x + threadIdx.x;
    if (e >= N_EDGES) return;
    int r, c;
    if (g_is64) {
        const long long* ei = (const long long*)eiv;
        r = (int)ei[e];
        c = (int)ei[N_EDGES + e];
    } else {
        const int* ei = (const int*)eiv;
        r = ei[e];
        c = ei[N_EDGES + e];
    }
    g_rowbuf[e] = r;
    g_colbuf[e] = c;
    atomicAdd(&g_cnt[c], 1);
}

// ---------------- parallel scan (3 phases) ----------------
__global__ __launch_bounds__(256)
void k_scanA() {
    int tid = threadIdx.x;
    int i = blockIdx.x * 256 + tid;
    int v = (i < N_NODES) ? g_cnt[i] : 0;
    int lane = tid & 31, wid = tid >> 5;
    int s = v;
    #pragma unroll
    for (int o = 1; o < 32; o <<= 1) {
        int t = __shfl_up_sync(0xFFFFFFFFu, s, o);
        if (lane >= o) s += t;
    }
    __shared__ int wsum[8];
    if (lane == 31) wsum[wid] = s;
    __syncthreads();
    if (wid == 0) {
        int ws = (lane < 8) ? wsum[lane] : 0;
        #pragma unroll
        for (int o = 1; o < 8; o <<= 1) {
            int t = __shfl_up_sync(0xFFFFFFFFu, ws, o);
            if (lane >= o) ws += t;
        }
        if (lane < 8) wsum[lane] = ws;
    }
    __syncthreads();
    int inc = s + ((wid > 0) ? wsum[wid - 1] : 0);
    if (i < N_NODES) g_off[i] = inc - v;
    if (tid == 255) g_bsum[blockIdx.x] = inc;
}

__global__ __launch_bounds__(256)
void k_scanB() {
    int tid = threadIdx.x;
    int v = (tid < SCAN_BLOCKS) ? g_bsum[tid] : 0;
    int lane = tid & 31, wid = tid >> 5;
    int s = v;
    #pragma unroll
    for (int o = 1; o < 32; o <<= 1) {
        int t = __shfl_up_sync(0xFFFFFFFFu, s, o);
        if (lane >= o) s += t;
    }
    __shared__ int wsum[8];
    if (lane == 31) wsum[wid] = s;
    __syncthreads();
    if (wid == 0) {
        int ws = (lane < 8) ? wsum[lane] : 0;
        #pragma unroll
        for (int o = 1; o < 8; o <<= 1) {
            int t = __shfl_up_sync(0xFFFFFFFFu, ws, o);
            if (lane >= o) ws += t;
        }
        if (lane < 8) wsum[lane] = ws;
    }
    __syncthreads();
    int inc = s + ((wid > 0) ? wsum[wid - 1] : 0);
    if (tid < SCAN_BLOCKS) g_boff[tid] = inc - v;
}

__global__ __launch_bounds__(256)
void k_scanC() {
    int i = blockIdx.x * 256 + threadIdx.x;
    if (i < N_NODES) {
        int o = g_off[i] + g_boff[blockIdx.x];
        g_off[i] = o;
        g_cur[i] = o;
    }
    if (i == 0) g_off[N_NODES] = N_EDGES;
}

__global__ void k_scatter() {
    int e = blockIdx.x * blockDim.x + threadIdx.x;
    if (e >= N_EDGES) return;
    int c = g_colbuf[e];
    int pos = atomicAdd(&g_cur[c], 1);
    g_esort[pos] = g_rowbuf[e];
}

// ---------------- Lorentz log map, warp per node, fp16 output ----------------
__global__ void k_logmap(const float* __restrict__ x) {
    int gw = (blockIdx.x * blockDim.x + threadIdx.x) >> 5;
    int lane = threadIdx.x & 31;
    if (gw >= N_NODES) return;
    const float* xr = x + (size_t)gw * 129;
    float a0 = xr[1 + 4 * lane + 0];
    float a1 = xr[1 + 4 * lane + 1];
    float a2 = xr[1 + 4 * lane + 2];
    float a3 = xr[1 + 4 * lane + 3];
    float ss = a0 * a0 + a1 * a1 + a2 * a2 + a3 * a3;
    #pragma unroll
    for (int o = 16; o >= 1; o >>= 1) ss += __shfl_xor_sync(0xFFFFFFFFu, ss, o);
    float norm = sqrtf(ss + EPSF);
    float fac = acoshf(fmaxf(xr[0], 1.0f + EPSF)) / norm;
    __half2 h0 = __float22half2_rn(make_float2(fac * a0, fac * a1));
    __half2 h1 = __float22half2_rn(make_float2(fac * a2, fac * a3));
    uint2 u;
    u.x = *reinterpret_cast<unsigned int*>(&h0);
    u.y = *reinterpret_cast<unsigned int*>(&h1);
    *(uint2*)(g_xtanh + (size_t)gw * D + 4 * lane) = u;
}

// ---------------- generic fp16 MMA GEMM (m16n8k16), 128x128 block ----------
// sel: 0=Q (fp16), 1=K (fp16 KV), 2=V (fp16 KV), 3=O (fp32 otan + bias)
__global__ __launch_bounds__(256, 2)
void k_gemm_mma(const __half* __restrict__ A,
                __half* __restrict__ Hout, __half* __restrict__ KV,
                float* __restrict__ Fout,
                const float* __restrict__ bias, int selArg, int M) {
    __shared__ __half As[128][72];   // stride 72 halves (odd 16B units) -> conflict-free ldmatrix
    __shared__ __half Bs[128][72];
    int sel = (selArg >= 0) ? selArg : (int)blockIdx.y;
    const __half* W = g_wh + (size_t)sel * D * D;
    int t = threadIdx.x;
    int warp = t >> 5, lane = t & 31;
    int warp_m = warp & 3;
    int warp_n = warp >> 2;
    int rowBase = blockIdx.x * 128;

    float acc[2][8][4];
    #pragma unroll
    for (int i = 0; i < 2; i++)
        #pragma unroll
        for (int j = 0; j < 8; j++)
            #pragma unroll
            for (int k = 0; k < 4; k++) acc[i][j][k] = 0.f;

    for (int k0 = 0; k0 < 128; k0 += 64) {
        __syncthreads();
        #pragma unroll
        for (int c = t; c < 1024; c += 256) {
            int r = c >> 3, c8 = (c & 7) * 8;
            int gr = rowBase + r;
            uint4 va = make_uint4(0u, 0u, 0u, 0u);
            if (gr < M) va = *(const uint4*)&A[(size_t)gr * 128 + k0 + c8];
            *(uint4*)&As[r][c8] = va;
            uint4 vb = *(const uint4*)&W[(size_t)r * 128 + k0 + c8];
            *(uint4*)&Bs[r][c8] = vb;
        }
        __syncthreads();
        #pragma unroll
        for (int kk = 0; kk < 4; kk++) {
            uint32_t af[2][4];
            #pragma unroll
            for (int mt = 0; mt < 2; mt++) {
                int sub = lane >> 3;
                int row = warp_m * 32 + mt * 16 + ((sub & 1) * 8) + (lane & 7);
                int col = kk * 16 + ((sub >> 1) * 8);
                uint32_t addr = (uint32_t)__cvta_generic_to_shared(&As[row][col]);
                asm volatile("ldmatrix.sync.aligned.m8n8.x4.shared.b16 {%0,%1,%2,%3}, [%4];"
                    : "=r"(af[mt][0]), "=r"(af[mt][1]), "=r"(af[mt][2]), "=r"(af[mt][3])
                    : "r"(addr));
            }
            uint32_t bf[8][2];
            #pragma unroll
            for (int np = 0; np < 4; np++) {
                int sub = lane >> 3;
                int row = warp_n * 64 + np * 16 + ((sub >> 1) * 8) + (lane & 7);
                int col = kk * 16 + ((sub & 1) * 8);
                uint32_t r0, r1, r2, r3;
                uint32_t addr = (uint32_t)__cvta_generic_to_shared(&Bs[row][col]);
                asm volatile("ldmatrix.sync.aligned.m8n8.x4.shared.b16 {%0,%1,%2,%3}, [%4];"
                    : "=r"(r0), "=r"(r1), "=r"(r2), "=r"(r3) : "r"(addr));
                bf[np * 2][0] = r0; bf[np * 2][1] = r1;
                bf[np * 2 + 1][0] = r2; bf[np * 2 + 1][1] = r3;
            }
            #pragma unroll
            for (int mt = 0; mt < 2; mt++)
                #pragma unroll
                for (int nt = 0; nt < 8; nt++)
                    asm volatile("mma.sync.aligned.m16n8k16.row.col.f32.f16.f16.f32 "
                        "{%0,%1,%2,%3}, {%4,%5,%6,%7}, {%8,%9}, {%0,%1,%2,%3};"
                        : "+f"(acc[mt][nt][0]), "+f"(acc[mt][nt][1]),
                          "+f"(acc[mt][nt][2]), "+f"(acc[mt][nt][3])
                        : "r"(af[mt][0]), "r"(af[mt][1]), "r"(af[mt][2]), "r"(af[mt][3]),
                          "r"(bf[nt][0]), "r"(bf[nt][1]));
        }
    }
    int g = lane >> 2, tg = lane & 3;
    #pragma unroll
    for (int mt = 0; mt < 2; mt++) {
        int r0 = rowBase + warp_m * 32 + mt * 16 + g;
        int r1 = r0 + 8;
        #pragma unroll
        for (int nt = 0; nt < 8; nt++) {
            int col = warp_n * 64 + nt * 8 + tg * 2;
            if (sel == 3) {               // otan fp32 + bias
                float b0 = bias[col], b1 = bias[col + 1];
                if (r0 < M) *(float2*)&Fout[(size_t)r0 * 128 + col] =
                    make_float2(acc[mt][nt][0] + b0, acc[mt][nt][1] + b1);
                if (r1 < M) *(float2*)&Fout[(size_t)r1 * 128 + col] =
                    make_float2(acc[mt][nt][2] + b0, acc[mt][nt][3] + b1);
            } else {
                __half2 h0 = __float22half2_rn(make_float2(acc[mt][nt][0], acc[mt][nt][1]));
                __half2 h1 = __float22half2_rn(make_float2(acc[mt][nt][2], acc[mt][nt][3]));
                if (sel == 0) {           // Q fp16
                    if (r0 < M) *(__half2*)&Hout[(size_t)r0 * 128 + col] = h0;
                    if (r1 < M) *(__half2*)&Hout[(size_t)r1 * 128 + col] = h1;
                } else {                  // K/V fp16
                    int off = (sel - 1) * 128;
                    if (r0 < M) *(__half2*)&KV[(size_t)r0 * 256 + off + col] = h0;
                    if (r1 < M) *(__half2*)&KV[(size_t)r1 * 256 + off + col] = h1;
                }
            }
        }
    }
}

// ---------------- fp16 gather helper ----------------
__device__ __forceinline__ float4 ld4h(const __half* p) {
    uint2 u = *(const uint2*)p;
    __half2 h0 = *reinterpret_cast<__half2*>(&u.x);
    __half2 h1 = *reinterpret_cast<__half2*>(&u.y);
    float2 f0 = __half22float2(h0);
    float2 f1 = __half22float2(h1);
    return make_float4(f0.x, f0.y, f1.x, f1.y);
}

// ---------------- CSR aggregation: warp per dst, 4-way unroll, fp16 I/O ----
__global__ __launch_bounds__(256)
void k_agg() {
    int gw = (blockIdx.x * blockDim.x + threadIdx.x) >> 5;
    int lane = threadIdx.x & 31;
    if (gw >= N_NODES) return;
    int start = g_off[gw];
    int end   = g_off[gw + 1];
    float4 q = ld4h(g_qh + (size_t)gw * 128 + 4 * lane);
    float4 acc = make_float4(0.f, 0.f, 0.f, 0.f);
    float dsum = 0.f;
    int i = start;
    for (; i + 4 <= end; i += 4) {
        int s0 = g_esort[i], s1 = g_esort[i + 1], s2 = g_esort[i + 2], s3 = g_esort[i + 3];
        const __half* b0 = g_kvh + (size_t)s0 * 256;
        const __half* b1 = g_kvh + (size_t)s1 * 256;
        const __half* b2 = g_kvh + (size_t)s2 * 256;
        const __half* b3 = g_kvh + (size_t)s3 * 256;
        float4 k0 = ld4h(b0 + 4 * lane);
        float4 k1 = ld4h(b1 + 4 * lane);
        float4 k2 = ld4h(b2 + 4 * lane);
        float4 k3 = ld4h(b3 + 4 * lane);
        float p0 = q.x * k0.x + q.y * k0.y + q.z * k0.z + q.w * k0.w;
        float p1 = q.x * k1.x + q.y * k1.y + q.z * k1.z + q.w * k1.w;
        float p2 = q.x * k2.x + q.y * k2.y + q.z * k2.z + q.w * k2.w;
        float p3 = q.x * k3.x + q.y * k3.y + q.z * k3.z + q.w * k3.w;
        #pragma unroll
        for (int o = 4; o >= 1; o >>= 1) {
            p0 += __shfl_xor_sync(0xFFFFFFFFu, p0, o);
            p1 += __shfl_xor_sync(0xFFFFFFFFu, p1, o);
            p2 += __shfl_xor_sync(0xFFFFFFFFu, p2, o);
            p3 += __shfl_xor_sync(0xFFFFFFFFu, p3, o);
        }
        float e0 = __expf(p0 * SCALEF);
        float e1 = __expf(p1 * SCALEF);
        float e2 = __expf(p2 * SCALEF);
        float e3 = __expf(p3 * SCALEF);
        float4 v0 = ld4h(b0 + 128 + 4 * lane);
        float4 v1 = ld4h(b1 + 128 + 4 * lane);
        float4 v2 = ld4h(b2 + 128 + 4 * lane);
        float4 v3 = ld4h(b3 + 128 + 4 * lane);
        dsum += (e0 + e1) + (e2 + e3);
        acc.x = fmaf(e0, v0.x, fmaf(e1, v1.x, fmaf(e2, v2.x, fmaf(e3, v3.x, acc.x))));
        acc.y = fmaf(e0, v0.y, fmaf(e1, v1.y, fmaf(e2, v2.y, fmaf(e3, v3.y, acc.y))));
        acc.z = fmaf(e0, v0.z, fmaf(e1, v1.z, fmaf(e2, v2.z, fmaf(e3, v3.z, acc.z))));
        acc.w = fmaf(e0, v0.w, fmaf(e1, v1.w, fmaf(e2, v2.w, fmaf(e3, v3.w, acc.w))));
    }
    for (; i < end; i++) {
        int s0 = g_esort[i];
        const __half* b0 = g_kvh + (size_t)s0 * 256;
        float4 k0 = ld4h(b0 + 4 * lane);
        float p0 = q.x * k0.x + q.y * k0.y + q.z * k0.z + q.w * k0.w;
        #pragma unroll
        for (int o = 4; o >= 1; o >>= 1) p0 += __shfl_xor_sync(0xFFFFFFFFu, p0, o);
        float e0 = __expf(p0 * SCALEF);
        float4 v0 = ld4h(b0 + 128 + 4 * lane);
        dsum += e0;
        acc.x = fmaf(e0, v0.x, acc.x);
        acc.y = fmaf(e0, v0.y, acc.y);
        acc.z = fmaf(e0, v0.z, acc.z);
        acc.w = fmaf(e0, v0.w, acc.w);
    }
    float inv = (dsum > 0.f) ? (1.0f / dsum) : 0.f;
    __half2 h0 = __float22half2_rn(make_float2(acc.x * inv, acc.y * inv));
    __half2 h1 = __float22half2_rn(make_float2(acc.z * inv, acc.w * inv));
    uint2 u;
    u.x = *reinterpret_cast<unsigned int*>(&h0);
    u.y = *reinterpret_cast<unsigned int*>(&h1);
    *(uint2*)(g_aggh + (size_t)gw * 128 + 4 * lane) = u;
}

// ---------------- Lorentz exp map, warp per node ----------------
__global__ void k_expmap(float* __restrict__ out) {
    int gw = (blockIdx.x * blockDim.x + threadIdx.x) >> 5;
    int lane = threadIdx.x & 31;
    if (gw >= N_NODES) return;
    const float* vr = g_otan + (size_t)gw * D;
    float4 v = *(const float4*)(vr + 4 * lane);
    float ss = v.x * v.x + v.y * v.y + v.z * v.z + v.w * v.w;
    #pragma unroll
    for (int o = 16; o >= 1; o >>= 1) ss += __shfl_xor_sync(0xFFFFFFFFu, ss, o);
    float r = sqrtf(ss + EPSF);
    float x0 = coshf(r);
    float fac = sinhf(r) / r;
    float* orow = out + (size_t)gw * 129;
    if (lane == 0) orow[0] = x0;
    orow[1 + 4 * lane + 0] = fac * v.x;
    orow[1 + 4 * lane + 1] = fac * v.y;
    orow[1 + 4 * lane + 2] = fac * v.z;
    orow[1 + 4 * lane + 3] = fac * v.w;
}

// ---------------- launch ----------------
extern "C" void kernel_launch(void* const* d_in, const int* in_sizes, int n_in,
                              void* d_out, int out_size) {
    const float* x  = (const float*)d_in[0];
    const void*  ei = (const void*)d_in[1];
    const float* Wq = (const float*)d_in[2];
    const float* Wk = (const float*)d_in[3];
    const float* Wv = (const float*)d_in[4];
    const float* Wo = (const float*)d_in[5];
    const float* bo = (const float*)d_in[6];
    float* out      = (float*)d_out;
    (void)in_sizes; (void)n_in; (void)out_size;

    // real device addresses of __device__ globals (ATS pitfall!)
    float *otan;
    __half *xtanh, *qh, *kvh, *aggh;
    cudaGetSymbolAddress((void**)&xtanh, g_xtanh);
    cudaGetSymbolAddress((void**)&qh,    g_qh);
    cudaGetSymbolAddress((void**)&kvh,   g_kvh);
    cudaGetSymbolAddress((void**)&aggh,  g_aggh);
    cudaGetSymbolAddress((void**)&otan,  g_otan);

    // prep: dtype detect + zero hist + W->fp16
    // grid MUST cover max(N_NODES, 4*D*D) = 65536 indices (R15 bug: only covered 50176)
    k_prep<<<(4 * D * D + 255) / 256, 256>>>((const unsigned int*)ei, Wq, Wk, Wv, Wo);
    // CSR build
    k_cvt_hist<<<(N_EDGES + 255) / 256, 256>>>(ei);
    k_scanA<<<SCAN_BLOCKS, 256>>>();
    k_scanB<<<1, 256>>>();
    k_scanC<<<SCAN_BLOCKS, 256>>>();
    k_scatter<<<(N_EDGES + 255) / 256, 256>>>();
    // log map -> fp16
    k_logmap<<<(N_NODES * 32 + 255) / 256, 256>>>(x);
    // QKV projection on tensor cores (grid.y = sel 0..2); Q fp16
    {
        dim3 grid((N_NODES + 127) / 128, 3);
        k_gemm_mma<<<grid, 256>>>(xtanh, qh, kvh, nullptr, nullptr, -1, N_NODES);
    }
    // attention aggregation (fp16 in/out)
    k_agg<<<(N_NODES * 32 + 255) / 256, 256>>>();
    // output projection on tensor cores (sel=3, bias, fp32 out)
    k_gemm_mma<<<(N_NODES + 127) / 128, 256>>>(aggh, nullptr, nullptr, otan, bo, 3, N_NODES);
    k_expmap<<<(N_NODES * 32 + 255) / 256, 256>>>(out);
}

// round 17
// speedup vs baseline: 1.4246x; 1.0146x over previous
#include <cuda_runtime.h>
#include <cuda_fp16.h>
#include <math.h>
#include <stdint.h>
#include <cstdint>

#define N_NODES 50000
#define N_EDGES 800000
#define D 128
#define SCALEF 0.17677669529663687f   // 32^-0.5
#define EPSF 1e-7f
#define SCAN_BLOCKS ((N_NODES + 255) / 256)   // 196

// ---------------- static device scratch ----------------
__device__ __half g_xtanh[(size_t)N_NODES * D];      // x_tan fp16 (GEMM A)
__device__ __half g_wh[4 * D * D];                   // Wq|Wk|Wv|Wo fp16
__device__ __half g_qh[(size_t)N_NODES * D];         // Q fp16
__device__ __half g_kvh[(size_t)N_NODES * 2 * D];    // per node: K(128)|V(128) fp16
__device__ __half g_aggh[(size_t)N_NODES * D];       // attention out fp16, normalized
__device__ int    g_rowbuf[N_EDGES];
__device__ int    g_colbuf[N_EDGES];
__device__ int    g_cnt[N_NODES];
__device__ int    g_off[N_NODES + 1];
__device__ int    g_cur[N_NODES];
__device__ int    g_esort[N_EDGES];
__device__ int    g_bsum[SCAN_BLOCKS];
__device__ int    g_is64;

// ---------------- prep: edge dtype detect + zero cnt + cvt W ----------------
// MUST be launched with >= max(N_NODES, 4*D*D) = 65536 threads.
__global__ __launch_bounds__(256)
void k_prep(const unsigned int* __restrict__ w,
            const float* __restrict__ Wq, const float* __restrict__ Wk,
            const float* __restrict__ Wv, const float* __restrict__ Wo) {
    int i = blockIdx.x * 256 + threadIdx.x;
    if (i == 0) {
        int all0 = 1;
        #pragma unroll
        for (int j = 0; j < 32; j++) all0 &= (w[2 * j + 1] == 0u);
        g_is64 = all0;
    }
    if (i < N_NODES) g_cnt[i] = 0;
    if (i < 4 * D * D) {
        int sel = i / (D * D);
        int off = i - sel * (D * D);
        float v = (sel == 0) ? Wq[off] : (sel == 1) ? Wk[off] : (sel == 2) ? Wv[off] : Wo[off];
        g_wh[i] = __float2half_rn(v);
    }
}

// ---------------- convert edges + histogram dst degrees ----------------
__global__ void k_cvt_hist(const void* __restrict__ eiv) {
    int e = blockIdx.x * blockDim.x + threadIdx.x;
    if (e >= N_EDGES) return;
    int r, c;
    if (g_is64) {
        const long long* ei = (const long long*)eiv;
        r = (int)ei[e];
        c = (int)ei[N_EDGES + e];
    } else {
        const int* ei = (const int*)eiv;
        r = ei[e];
        c = ei[N_EDGES + e];
    }
    g_rowbuf[e] = r;
    g_colbuf[e] = c;
    atomicAdd(&g_cnt[c], 1);
}

// ---------------- parallel scan, phase A: block scans ----------------
__global__ __launch_bounds__(256)
void k_scanA() {
    int tid = threadIdx.x;
    int i = blockIdx.x * 256 + tid;
    int v = (i < N_NODES) ? g_cnt[i] : 0;
    int lane = tid & 31, wid = tid >> 5;
    int s = v;
    #pragma unroll
    for (int o = 1; o < 32; o <<= 1) {
        int t = __shfl_up_sync(0xFFFFFFFFu, s, o);
        if (lane >= o) s += t;
    }
    __shared__ int wsum[8];
    if (lane == 31) wsum[wid] = s;
    __syncthreads();
    if (wid == 0) {
        int ws = (lane < 8) ? wsum[lane] : 0;
        #pragma unroll
        for (int o = 1; o < 8; o <<= 1) {
            int t = __shfl_up_sync(0xFFFFFFFFu, ws, o);
            if (lane >= o) ws += t;
        }
        if (lane < 8) wsum[lane] = ws;
    }
    __syncthreads();
    int inc = s + ((wid > 0) ? wsum[wid - 1] : 0);
    if (i < N_NODES) g_off[i] = inc - v;
    if (tid == 255) g_bsum[blockIdx.x] = inc;
}

// ---------------- phase B+C merged: each block computes its own offset -----
__global__ __launch_bounds__(256)
void k_scanBC() {
    int tid = threadIdx.x;
    // sum of block sums strictly before this block (<=196 values, 1 per thread)
    int v = (tid < SCAN_BLOCKS && tid < (int)blockIdx.x) ? g_bsum[tid] : 0;
    int lane = tid & 31, wid = tid >> 5;
    #pragma unroll
    for (int o = 16; o >= 1; o >>= 1) v += __shfl_xor_sync(0xFFFFFFFFu, v, o);
    __shared__ int wsum[8];
    if (lane == 0) wsum[wid] = v;
    __syncthreads();
    __shared__ int boff_sh;
    if (tid == 0) {
        int s = 0;
        #pragma unroll
        for (int j = 0; j < 8; j++) s += wsum[j];
        boff_sh = s;
    }
    __syncthreads();
    int boff = boff_sh;
    int i = blockIdx.x * 256 + tid;
    if (i < N_NODES) {
        int o = g_off[i] + boff;
        g_off[i] = o;
        g_cur[i] = o;
    }
    if (i == 0) g_off[N_NODES] = N_EDGES;
}

__global__ void k_scatter() {
    int e = blockIdx.x * blockDim.x + threadIdx.x;
    if (e >= N_EDGES) return;
    int c = g_colbuf[e];
    int pos = atomicAdd(&g_cur[c], 1);
    g_esort[pos] = g_rowbuf[e];
}

// ---------------- Lorentz log map, warp per node, fp16 output ----------------
__global__ void k_logmap(const float* __restrict__ x) {
    int gw = (blockIdx.x * blockDim.x + threadIdx.x) >> 5;
    int lane = threadIdx.x & 31;
    if (gw >= N_NODES) return;
    const float* xr = x + (size_t)gw * 129;
    float a0 = xr[1 + 4 * lane + 0];
    float a1 = xr[1 + 4 * lane + 1];
    float a2 = xr[1 + 4 * lane + 2];
    float a3 = xr[1 + 4 * lane + 3];
    float ss = a0 * a0 + a1 * a1 + a2 * a2 + a3 * a3;
    #pragma unroll
    for (int o = 16; o >= 1; o >>= 1) ss += __shfl_xor_sync(0xFFFFFFFFu, ss, o);
    float norm = sqrtf(ss + EPSF);
    float fac = acoshf(fmaxf(xr[0], 1.0f + EPSF)) / norm;
    __half2 h0 = __float22half2_rn(make_float2(fac * a0, fac * a1));
    __half2 h1 = __float22half2_rn(make_float2(fac * a2, fac * a3));
    uint2 u;
    u.x = *reinterpret_cast<unsigned int*>(&h0);
    u.y = *reinterpret_cast<unsigned int*>(&h1);
    *(uint2*)(g_xtanh + (size_t)gw * D + 4 * lane) = u;
}

// ---------------- QKV MMA GEMM (m16n8k16), 128x128 block, sel=blockIdx.y ----
__global__ __launch_bounds__(256, 2)
void k_gemm_qkv(const __half* __restrict__ A,
                __half* __restrict__ Qh, __half* __restrict__ KV, int M) {
    __shared__ __half As[128][72];   // odd 16B-unit stride -> conflict-free ldmatrix
    __shared__ __half Bs[128][72];
    int sel = blockIdx.y;
    const __half* W = g_wh + (size_t)sel * D * D;
    int t = threadIdx.x;
    int warp = t >> 5, lane = t & 31;
    int warp_m = warp & 3;
    int warp_n = warp >> 2;
    int rowBase = blockIdx.x * 128;

    float acc[2][8][4];
    #pragma unroll
    for (int i = 0; i < 2; i++)
        #pragma unroll
        for (int j = 0; j < 8; j++)
            #pragma unroll
            for (int k = 0; k < 4; k++) acc[i][j][k] = 0.f;

    for (int k0 = 0; k0 < 128; k0 += 64) {
        __syncthreads();
        #pragma unroll
        for (int c = t; c < 1024; c += 256) {
            int r = c >> 3, c8 = (c & 7) * 8;
            int gr = rowBase + r;
            uint4 va = make_uint4(0u, 0u, 0u, 0u);
            if (gr < M) va = *(const uint4*)&A[(size_t)gr * 128 + k0 + c8];
            *(uint4*)&As[r][c8] = va;
            uint4 vb = *(const uint4*)&W[(size_t)r * 128 + k0 + c8];
            *(uint4*)&Bs[r][c8] = vb;
        }
        __syncthreads();
        #pragma unroll
        for (int kk = 0; kk < 4; kk++) {
            uint32_t af[2][4];
            #pragma unroll
            for (int mt = 0; mt < 2; mt++) {
                int sub = lane >> 3;
                int row = warp_m * 32 + mt * 16 + ((sub & 1) * 8) + (lane & 7);
                int col = kk * 16 + ((sub >> 1) * 8);
                uint32_t addr = (uint32_t)__cvta_generic_to_shared(&As[row][col]);
                asm volatile("ldmatrix.sync.aligned.m8n8.x4.shared.b16 {%0,%1,%2,%3}, [%4];"
                    : "=r"(af[mt][0]), "=r"(af[mt][1]), "=r"(af[mt][2]), "=r"(af[mt][3])
                    : "r"(addr));
            }
            uint32_t bf[8][2];
            #pragma unroll
            for (int np = 0; np < 4; np++) {
                int sub = lane >> 3;
                int row = warp_n * 64 + np * 16 + ((sub >> 1) * 8) + (lane & 7);
                int col = kk * 16 + ((sub & 1) * 8);
                uint32_t r0, r1, r2, r3;
                uint32_t addr = (uint32_t)__cvta_generic_to_shared(&Bs[row][col]);
                asm volatile("ldmatrix.sync.aligned.m8n8.x4.shared.b16 {%0,%1,%2,%3}, [%4];"
                    : "=r"(r0), "=r"(r1), "=r"(r2), "=r"(r3) : "r"(addr));
                bf[np * 2][0] = r0; bf[np * 2][1] = r1;
                bf[np * 2 + 1][0] = r2; bf[np * 2 + 1][1] = r3;
            }
            #pragma unroll
            for (int mt = 0; mt < 2; mt++)
                #pragma unroll
                for (int nt = 0; nt < 8; nt++)
                    asm volatile("mma.sync.aligned.m16n8k16.row.col.f32.f16.f16.f32 "
                        "{%0,%1,%2,%3}, {%4,%5,%6,%7}, {%8,%9}, {%0,%1,%2,%3};"
                        : "+f"(acc[mt][nt][0]), "+f"(acc[mt][nt][1]),
                          "+f"(acc[mt][nt][2]), "+f"(acc[mt][nt][3])
                        : "r"(af[mt][0]), "r"(af[mt][1]), "r"(af[mt][2]), "r"(af[mt][3]),
                          "r"(bf[nt][0]), "r"(bf[nt][1]));
        }
    }
    int g = lane >> 2, tg = lane & 3;
    #pragma unroll
    for (int mt = 0; mt < 2; mt++) {
        int r0 = rowBase + warp_m * 32 + mt * 16 + g;
        int r1 = r0 + 8;
        #pragma unroll
        for (int nt = 0; nt < 8; nt++) {
            int col = warp_n * 64 + nt * 8 + tg * 2;
            __half2 h0 = __float22half2_rn(make_float2(acc[mt][nt][0], acc[mt][nt][1]));
            __half2 h1 = __float22half2_rn(make_float2(acc[mt][nt][2], acc[mt][nt][3]));
            if (sel == 0) {
                if (r0 < M) *(__half2*)&Qh[(size_t)r0 * 128 + col] = h0;
                if (r1 < M) *(__half2*)&Qh[(size_t)r1 * 128 + col] = h1;
            } else {
                int off = (sel - 1) * 128;
                if (r0 < M) *(__half2*)&KV[(size_t)r0 * 256 + off + col] = h0;
                if (r1 < M) *(__half2*)&KV[(size_t)r1 * 256 + off + col] = h1;
            }
        }
    }
}

// ---------------- fp16 gather helper ----------------
__device__ __forceinline__ float4 ld4h(const __half* p) {
    uint2 u = *(const uint2*)p;
    __half2 h0 = *reinterpret_cast<__half2*>(&u.x);
    __half2 h1 = *reinterpret_cast<__half2*>(&u.y);
    float2 f0 = __half22float2(h0);
    float2 f1 = __half22float2(h1);
    return make_float4(f0.x, f0.y, f1.x, f1.y);
}

// ---------------- CSR aggregation: warp per dst, 4-way unroll, fp16 I/O ----
__global__ __launch_bounds__(256)
void k_agg() {
    int gw = (blockIdx.x * blockDim.x + threadIdx.x) >> 5;
    int lane = threadIdx.x & 31;
    if (gw >= N_NODES) return;
    int start = g_off[gw];
    int end   = g_off[gw + 1];
    float4 q = ld4h(g_qh + (size_t)gw * 128 + 4 * lane);
    float4 acc = make_float4(0.f, 0.f, 0.f, 0.f);
    float dsum = 0.f;
    int i = start;
    for (; i + 4 <= end; i += 4) {
        int s0 = g_esort[i], s1 = g_esort[i + 1], s2 = g_esort[i + 2], s3 = g_esort[i + 3];
        const __half* b0 = g_kvh + (size_t)s0 * 256;
        const __half* b1 = g_kvh + (size_t)s1 * 256;
        const __half* b2 = g_kvh + (size_t)s2 * 256;
        const __half* b3 = g_kvh + (size_t)s3 * 256;
        float4 k0 = ld4h(b0 + 4 * lane);
        float4 k1 = ld4h(b1 + 4 * lane);
        float4 k2 = ld4h(b2 + 4 * lane);
        float4 k3 = ld4h(b3 + 4 * lane);
        float p0 = q.x * k0.x + q.y * k0.y + q.z * k0.z + q.w * k0.w;
        float p1 = q.x * k1.x + q.y * k1.y + q.z * k1.z + q.w * k1.w;
        float p2 = q.x * k2.x + q.y * k2.y + q.z * k2.z + q.w * k2.w;
        float p3 = q.x * k3.x + q.y * k3.y + q.z * k3.z + q.w * k3.w;
        #pragma unroll
        for (int o = 4; o >= 1; o >>= 1) {
            p0 += __shfl_xor_sync(0xFFFFFFFFu, p0, o);
            p1 += __shfl_xor_sync(0xFFFFFFFFu, p1, o);
            p2 += __shfl_xor_sync(0xFFFFFFFFu, p2, o);
            p3 += __shfl_xor_sync(0xFFFFFFFFu, p3, o);
        }
        float e0 = __expf(p0 * SCALEF);
        float e1 = __expf(p1 * SCALEF);
        float e2 = __expf(p2 * SCALEF);
        float e3 = __expf(p3 * SCALEF);
        float4 v0 = ld4h(b0 + 128 + 4 * lane);
        float4 v1 = ld4h(b1 + 128 + 4 * lane);
        float4 v2 = ld4h(b2 + 128 + 4 * lane);
        float4 v3 = ld4h(b3 + 128 + 4 * lane);
        dsum += (e0 + e1) + (e2 + e3);
        acc.x = fmaf(e0, v0.x, fmaf(e1, v1.x, fmaf(e2, v2.x, fmaf(e3, v3.x, acc.x))));
        acc.y = fmaf(e0, v0.y, fmaf(e1, v1.y, fmaf(e2, v2.y, fmaf(e3, v3.y, acc.y))));
        acc.z = fmaf(e0, v0.z, fmaf(e1, v1.z, fmaf(e2, v2.z, fmaf(e3, v3.z, acc.z))));
        acc.w = fmaf(e0, v0.w, fmaf(e1, v1.w, fmaf(e3, v3.w, fmaf(e2, v2.w, acc.w))));
    }
    for (; i < end; i++) {
        int s0 = g_esort[i];
        const __half* b0 = g_kvh + (size_t)s0 * 256;
        float4 k0 = ld4h(b0 + 4 * lane);
        float p0 = q.x * k0.x + q.y * k0.y + q.z * k0.z + q.w * k0.w;
        #pragma unroll
        for (int o = 4; o >= 1; o >>= 1) p0 += __shfl_xor_sync(0xFFFFFFFFu, p0, o);
        float e0 = __expf(p0 * SCALEF);
        float4 v0 = ld4h(b0 + 128 + 4 * lane);
        dsum += e0;
        acc.x = fmaf(e0, v0.x, acc.x);
        acc.y = fmaf(e0, v0.y, acc.y);
        acc.z = fmaf(e0, v0.z, acc.z);
        acc.w = fmaf(e0, v0.w, acc.w);
    }
    float inv = (dsum > 0.f) ? (1.0f / dsum) : 0.f;
    __half2 h0 = __float22half2_rn(make_float2(acc.x * inv, acc.y * inv));
    __half2 h1 = __float22half2_rn(make_float2(acc.z * inv, acc.w * inv));
    uint2 u;
    u.x = *reinterpret_cast<unsigned int*>(&h0);
    u.y = *reinterpret_cast<unsigned int*>(&h1);
    *(uint2*)(g_aggh + (size_t)gw * 128 + 4 * lane) = u;
}

// ---------------- output GEMM (mma) + bias + exp map -> final (N,129) ------
// Cross-warp row ssq via 1KB smem; no big tile buffer (R14 lesson).
__global__ __launch_bounds__(256, 2)
void k_gemmO_exp(const __half* __restrict__ A, const float* __restrict__ bias,
                 float* __restrict__ out, int M) {
    __shared__ __half As[128][72];
    __shared__ __half Bs[128][72];
    __shared__ float ssq[128][2];
    const __half* W = g_wh + (size_t)3 * D * D;
    int t = threadIdx.x;
    int warp = t >> 5, lane = t & 31;
    int warp_m = warp & 3;
    int warp_n = warp >> 2;
    int rowBase = blockIdx.x * 128;

    float acc[2][8][4];
    #pragma unroll
    for (int i = 0; i < 2; i++)
        #pragma unroll
        for (int j = 0; j < 8; j++)
            #pragma unroll
            for (int k = 0; k < 4; k++) acc[i][j][k] = 0.f;

    for (int k0 = 0; k0 < 128; k0 += 64) {
        __syncthreads();
        #pragma unroll
        for (int c = t; c < 1024; c += 256) {
            int r = c >> 3, c8 = (c & 7) * 8;
            int gr = rowBase + r;
            uint4 va = make_uint4(0u, 0u, 0u, 0u);
            if (gr < M) va = *(const uint4*)&A[(size_t)gr * 128 + k0 + c8];
            *(uint4*)&As[r][c8] = va;
            uint4 vb = *(const uint4*)&W[(size_t)r * 128 + k0 + c8];
            *(uint4*)&Bs[r][c8] = vb;
        }
        __syncthreads();
        #pragma unroll
        for (int kk = 0; kk < 4; kk++) {
            uint32_t af[2][4];
            #pragma unroll
            for (int mt = 0; mt < 2; mt++) {
                int sub = lane >> 3;
                int row = warp_m * 32 + mt * 16 + ((sub & 1) * 8) + (lane & 7);
                int col = kk * 16 + ((sub >> 1) * 8);
                uint32_t addr = (uint32_t)__cvta_generic_to_shared(&As[row][col]);
                asm volatile("ldmatrix.sync.aligned.m8n8.x4.shared.b16 {%0,%1,%2,%3}, [%4];"
                    : "=r"(af[mt][0]), "=r"(af[mt][1]), "=r"(af[mt][2]), "=r"(af[mt][3])
                    : "r"(addr));
            }
            uint32_t bf[8][2];
            #pragma unroll
            for (int np = 0; np < 4; np++) {
                int sub = lane >> 3;
                int row = warp_n * 64 + np * 16 + ((sub >> 1) * 8) + (lane & 7);
                int col = kk * 16 + ((sub & 1) * 8);
                uint32_t r0, r1, r2, r3;
                uint32_t addr = (uint32_t)__cvta_generic_to_shared(&Bs[row][col]);
                asm volatile("ldmatrix.sync.aligned.m8n8.x4.shared.b16 {%0,%1,%2,%3}, [%4];"
                    : "=r"(r0), "=r"(r1), "=r"(r2), "=r"(r3) : "r"(addr));
                bf[np * 2][0] = r0; bf[np * 2][1] = r1;
                bf[np * 2 + 1][0] = r2; bf[np * 2 + 1][1] = r3;
            }
            #pragma unroll
            for (int mt = 0; mt < 2; mt++)
                #pragma unroll
                for (int nt = 0; nt < 8; nt++)
                    asm volatile("mma.sync.aligned.m16n8k16.row.col.f32.f16.f16.f32 "
                        "{%0,%1,%2,%3}, {%4,%5,%6,%7}, {%8,%9}, {%0,%1,%2,%3};"
                        : "+f"(acc[mt][nt][0]), "+f"(acc[mt][nt][1]),
                          "+f"(acc[mt][nt][2]), "+f"(acc[mt][nt][3])
                        : "r"(af[mt][0]), "r"(af[mt][1]), "r"(af[mt][2]), "r"(af[mt][3]),
                          "r"(bf[nt][0]), "r"(bf[nt][1]));
        }
    }
    int g = lane >> 2, tg = lane & 3;
    // bias + per-row partial sum of squares over this warp's 64-col half
    #pragma unroll
    for (int mt = 0; mt < 2; mt++) {
        float s0 = 0.f, s1 = 0.f;
        #pragma unroll
        for (int nt = 0; nt < 8; nt++) {
            int col = warp_n * 64 + nt * 8 + tg * 2;
            float b0 = bias[col], b1 = bias[col + 1];
            acc[mt][nt][0] += b0; acc[mt][nt][1] += b1;
            acc[mt][nt][2] += b0; acc[mt][nt][3] += b1;
            s0 += acc[mt][nt][0] * acc[mt][nt][0] + acc[mt][nt][1] * acc[mt][nt][1];
            s1 += acc[mt][nt][2] * acc[mt][nt][2] + acc[mt][nt][3] * acc[mt][nt][3];
        }
        // reduce over tg group (lanes g*4 + 0..3)
        s0 += __shfl_xor_sync(0xFFFFFFFFu, s0, 1);
        s0 += __shfl_xor_sync(0xFFFFFFFFu, s0, 2);
        s1 += __shfl_xor_sync(0xFFFFFFFFu, s1, 1);
        s1 += __shfl_xor_sync(0xFFFFFFFFu, s1, 2);
        if (tg == 0) {
            ssq[warp_m * 32 + mt * 16 + g][warp_n]     = s0;
            ssq[warp_m * 32 + mt * 16 + g + 8][warp_n] = s1;
        }
    }
    __syncthreads();
    #pragma unroll
    for (int mt = 0; mt < 2; mt++) {
        int lr0 = warp_m * 32 + mt * 16 + g;
        int lr1 = lr0 + 8;
        int gr0 = rowBase + lr0;
        int gr1 = rowBase + lr1;
        float t0 = ssq[lr0][0] + ssq[lr0][1];
        float t1 = ssq[lr1][0] + ssq[lr1][1];
        float r0 = sqrtf(t0 + EPSF);
        float r1 = sqrtf(t1 + EPSF);
        float f0 = sinhf(r0) / r0;
        float f1 = sinhf(r1) / r1;
        if (gr0 < M) {
            float* orow = out + (size_t)gr0 * 129;
            if (tg == 0 && warp_n == 0) orow[0] = coshf(r0);
            #pragma unroll
            for (int nt = 0; nt < 8; nt++) {
                int col = warp_n * 64 + nt * 8 + tg * 2;
                orow[1 + col]     = f0 * acc[mt][nt][0];
                orow[2 + col]     = f0 * acc[mt][nt][1];
            }
        }
        if (gr1 < M) {
            float* orow = out + (size_t)gr1 * 129;
            if (tg == 0 && warp_n == 0) orow[0] = coshf(r1);
            #pragma unroll
            for (int nt = 0; nt < 8; nt++) {
                int col = warp_n * 64 + nt * 8 + tg * 2;
                orow[1 + col]     = f1 * acc[mt][nt][2];
                orow[2 + col]     = f1 * acc[mt][nt][3];
            }
        }
    }
}

// ---------------- launch ----------------
extern "C" void kernel_launch(void* const* d_in, const int* in_sizes, int n_in,
                              void* d_out, int out_size) {
    const float* x  = (const float*)d_in[0];
    const void*  ei = (const void*)d_in[1];
    const float* Wq = (const float*)d_in[2];
    const float* Wk = (const float*)d_in[3];
    const float* Wv = (const float*)d_in[4];
    const float* Wo = (const float*)d_in[5];
    const float* bo = (const float*)d_in[6];
    float* out      = (float*)d_out;
    (void)in_sizes; (void)n_in; (void)out_size;

    // real device addresses of __device__ globals (ATS pitfall!)
    __half *xtanh, *qh, *kvh, *aggh;
    cudaGetSymbolAddress((void**)&xtanh, g_xtanh);
    cudaGetSymbolAddress((void**)&qh,    g_qh);
    cudaGetSymbolAddress((void**)&kvh,   g_kvh);
    cudaGetSymbolAddress((void**)&aggh,  g_aggh);

    // prep: grid MUST cover max(N_NODES, 4*D*D) = 65536 indices
    k_prep<<<(4 * D * D + 255) / 256, 256>>>((const unsigned int*)ei, Wq, Wk, Wv, Wo);
    // CSR build
    k_cvt_hist<<<(N_EDGES + 255) / 256, 256>>>(ei);
    k_scanA<<<SCAN_BLOCKS, 256>>>();
    k_scanBC<<<SCAN_BLOCKS, 256>>>();
    k_scatter<<<(N_EDGES + 255) / 256, 256>>>();
    // log map -> fp16
    k_logmap<<<(N_NODES * 32 + 255) / 256, 256>>>(x);
    // QKV projection on tensor cores (grid.y = sel 0..2)
    {
        dim3 grid((N_NODES + 127) / 128, 3);
        k_gemm_qkv<<<grid, 256>>>(xtanh, qh, kvh, N_NODES);
    }
    // attention aggregation (fp16 in/out)
    k_agg<<<(N_NODES * 32 + 255) / 256, 256>>>();
    // output projection + bias + exp map -> final output
    k_gemmO_exp<<<(N_NODES + 127) / 128, 256>>>(aggh, bo, out, N_NODES);
}